// round 7
// baseline (speedup 1.0000x reference)
#include <cuda_runtime.h>
#include <cuda_bf16.h>

#define FULL_MASK 0xffffffffu

constexpr int FDIM = 512;
constexpr int KDIM = 128;
constexpr int MT   = 64;          // rows per CTA
constexpr int BMAX = 65536;
constexpr float BN_EPS = 1e-3f;

// ---- scratch (device globals: allocation-free) ----
__device__ __nv_bfloat16 g_Ah[(size_t)BMAX * KDIM];
__device__ __nv_bfloat16 g_Al[(size_t)BMAX * KDIM];
__device__ __nv_bfloat16 g_Wh[(size_t)FDIM * KDIM];   // [f][k], k contiguous
__device__ __nv_bfloat16 g_Wl[(size_t)FDIM * KDIM];

// ---- smem layout (bytes) ----
constexpr int SM_ABF_HI = 0;
constexpr int SM_ABF_LO = 16384;
constexpr int SM_AT     = 32768;          // fp32 transpose, stride 65 floats
constexpr int AT_STRIDE = 65;
constexpr int SM_WBF0   = 66560;
constexpr int SM_WBF1   = 82944;
constexpr int SM_WF0    = 99328;
constexpr int SM_WF1    = 115712;
constexpr int ZSTRIDE   = 516;            // floats
constexpr int SM_SS     = 132608;
constexpr int SM_TT     = 134656;
constexpr int SMEM_BYTES = 136704;

// ---- PTX helpers (base ISA only) ----
__device__ __forceinline__ unsigned smem_u32(const void* p) {
    unsigned a;
    asm("{ .reg .u64 t; cvta.to.shared.u64 t, %1; cvt.u32.u64 %0, t; }" : "=r"(a) : "l"(p));
    return a;
}
__device__ __forceinline__ void cpa16(unsigned dst, const void* src) {
    asm volatile("cp.async.cg.shared.global [%0], [%1], 16;" :: "r"(dst), "l"(src));
}
__device__ __forceinline__ void cp_commit() {
    asm volatile("cp.async.commit_group;" ::: "memory");
}
__device__ __forceinline__ void cp_wait0() {
    asm volatile("cp.async.wait_group 0;" ::: "memory");
}
__device__ __forceinline__ void ldsm4(unsigned* r, unsigned addr) {
    asm volatile("ldmatrix.sync.aligned.m8n8.x4.shared.b16 {%0,%1,%2,%3}, [%4];"
        : "=r"(r[0]), "=r"(r[1]), "=r"(r[2]), "=r"(r[3]) : "r"(addr));
}
__device__ __forceinline__ void ldsm2(unsigned* r, unsigned addr) {
    asm volatile("ldmatrix.sync.aligned.m8n8.x2.shared.b16 {%0,%1}, [%2];"
        : "=r"(r[0]), "=r"(r[1]) : "r"(addr));
}
__device__ __forceinline__ void mma16816(float* d, const unsigned* a, const unsigned* b) {
    asm volatile(
        "mma.sync.aligned.m16n8k16.row.col.f32.bf16.bf16.f32 "
        "{%0,%1,%2,%3},{%4,%5,%6,%7},{%8,%9},{%0,%1,%2,%3};"
        : "+f"(d[0]), "+f"(d[1]), "+f"(d[2]), "+f"(d[3])
        : "r"(a[0]), "r"(a[1]), "r"(a[2]), "r"(a[3]), "r"(b[0]), "r"(b[1]));
}

// ================= conversion kernels =================
__global__ void conv_W_kernel(const float* __restrict__ W) {
    int idx = blockIdx.x * blockDim.x + threadIdx.x;   // 65536
    int k = idx >> 9;
    int f = idx & 511;
    float x = W[(size_t)k * FDIM + f];
    __nv_bfloat16 hi = __float2bfloat16(x);
    __nv_bfloat16 lo = __float2bfloat16(x - __bfloat162float(hi));
    g_Wh[(size_t)f * KDIM + k] = hi;
    g_Wl[(size_t)f * KDIM + k] = lo;
}

__global__ void conv_A_kernel(const float* __restrict__ A, int n2) {
    int i = blockIdx.x * blockDim.x + threadIdx.x;     // over float2's
    if (i >= n2) return;
    float2 x = ((const float2*)A)[i];
    __nv_bfloat16 h0 = __float2bfloat16(x.x);
    __nv_bfloat16 l0 = __float2bfloat16(x.x - __bfloat162float(h0));
    __nv_bfloat16 h1 = __float2bfloat16(x.y);
    __nv_bfloat16 l1 = __float2bfloat16(x.y - __bfloat162float(h1));
    __nv_bfloat162 hh; hh.x = h0; hh.y = h1;
    __nv_bfloat162 ll; ll.x = l0; ll.y = l1;
    ((__nv_bfloat162*)g_Ah)[i] = hh;
    ((__nv_bfloat162*)g_Al)[i] = ll;
}

// ================= main fused kernel =================
__global__ __launch_bounds__(512, 1)
void attn_dual_kernel(const float* __restrict__ A,      // fp32 [B,128]
                      const float* __restrict__ prior,
                      const float* __restrict__ W,      // fp32 [128,512]
                      const float* __restrict__ bias,
                      const float* __restrict__ gamma,
                      const float* __restrict__ beta,
                      const float* __restrict__ mmean,
                      const float* __restrict__ mvar,
                      float* __restrict__ out) {
    extern __shared__ char sm[];
    const unsigned smb = smem_u32(sm);
    float* sS = (float*)(sm + SM_SS);
    float* sT = (float*)(sm + SM_TT);
    float* At = (float*)(sm + SM_AT);

    const int tid  = threadIdx.x;
    const int wid  = tid >> 5;
    const int lane = tid & 31;
    const int rowbase = blockIdx.x * MT;

    // BN constants (bias folded): z = dot*s + t
    {
        float s = gamma[tid] * rsqrtf(mvar[tid] + BN_EPS);
        sS[tid] = s;
        sT[tid] = (bias[tid] - mmean[tid]) * s + beta[tid];
    }

    // ---- prologue staging ----
#pragma unroll
    for (int p = 0; p < 4; p++) {
        int j   = p * 512 + tid;          // 2048 x uint4
        int sel = j >> 10;                // 0=hi 1=lo
        int rem = j & 1023;
        int r   = rem >> 4;
        int k8  = rem & 15;
        const __nv_bfloat16* src =
            (sel ? g_Al : g_Ah) + (size_t)(rowbase + r) * KDIM + k8 * 8;
        unsigned dst = smb + (sel ? SM_ABF_LO : SM_ABF_HI)
                     + r * 256 + ((k8 * 16) ^ ((r & 7) << 4));
        cpa16(dst, src);
    }
    {   // W chunk 0: bf16 cols 0..255 + fp32 cols 256..511
#pragma unroll
        for (int p = 0; p < 2; p++) {     // Wbf: 1024 x uint4
            int j   = p * 512 + tid;
            int sel = j >> 9;
            int rem = j & 511;
            int n   = rem >> 1;
            int h   = rem & 1;
            const __nv_bfloat16* src =
                (sel ? g_Wl : g_Wh) + (size_t)n * KDIM + 0 * 16 + h * 8;
            unsigned dst = smb + SM_WBF0 + (sel ? 8192 : 0)
                         + n * 32 + ((h * 16) ^ (((n >> 2) & 1) << 4));
            cpa16(dst, src);
        }
#pragma unroll
        for (int p = 0; p < 2; p++) {     // Wf32: 1024 x float4
            int j  = p * 512 + tid;
            int k  = j >> 6;
            int c4 = j & 63;
            const float* src = W + (size_t)(0 * 16 + k) * FDIM + 256 + c4 * 4;
            unsigned dst = smb + SM_WF0 + k * 1024 + c4 * 16;
            cpa16(dst, src);
        }
    }
    // A_t fp32 transpose (LDG.128 + scalar STS), stride 65 (conflict-spread)
#pragma unroll
    for (int p = 0; p < 4; p++) {
        int j  = p * 512 + tid;           // 2048 x float4
        int r  = j >> 5;
        int c4 = j & 31;
        float4 v = ((const float4*)A)[(size_t)(rowbase + r) * 32 + c4];
        At[(c4 * 4 + 0) * AT_STRIDE + r] = v.x;
        At[(c4 * 4 + 1) * AT_STRIDE + r] = v.y;
        At[(c4 * 4 + 2) * AT_STRIDE + r] = v.z;
        At[(c4 * 4 + 3) * AT_STRIDE + r] = v.w;
    }
    cp_commit();

    float acc[64];                        // tensor: [(sub*8+j)*4+c]  ffma: [i*8+j]
#pragma unroll
    for (int i = 0; i < 64; i++) acc[i] = 0.f;

    const int wm = wid >> 2;              // tensor: m-block (0..1)
    const int wn = wid & 3;               // tensor: n64 slice of 256
    const int fw = wid - 8;               // ffma warp id 0..7
    const int rgrp = lane >> 2;           // ffma rows rgrp*8..+8
    const int cg = lane & 3;              // ffma cols fw*32 + cg*8 ..+8

    // ---- K loop: 8 chunks of 16, double-buffered W ----
#pragma unroll 1
    for (int kc = 0; kc < 8; kc++) {
        cp_wait0();
        __syncthreads();
        if (kc < 7) {
            const int pbuf = (kc + 1) & 1;
            const int wbf = pbuf ? SM_WBF1 : SM_WBF0;
            const int wf  = pbuf ? SM_WF1  : SM_WF0;
#pragma unroll
            for (int p = 0; p < 2; p++) {
                int j   = p * 512 + tid;
                int sel = j >> 9;
                int rem = j & 511;
                int n   = rem >> 1;
                int h   = rem & 1;
                const __nv_bfloat16* src =
                    (sel ? g_Wl : g_Wh) + (size_t)n * KDIM + (kc + 1) * 16 + h * 8;
                unsigned dst = smb + wbf + (sel ? 8192 : 0)
                             + n * 32 + ((h * 16) ^ (((n >> 2) & 1) << 4));
                cpa16(dst, src);
            }
#pragma unroll
            for (int p = 0; p < 2; p++) {
                int j  = p * 512 + tid;
                int k  = j >> 6;
                int c4 = j & 63;
                const float* src = W + (size_t)((kc + 1) * 16 + k) * FDIM + 256 + c4 * 4;
                unsigned dst = smb + wf + k * 1024 + c4 * 16;
                cpa16(dst, src);
            }
            cp_commit();
        }

        if (wid < 8) {
            // ===== tensor warps: cols 0..255, 3-pass bf16 =====
            const unsigned wb = smb + ((kc & 1) ? SM_WBF1 : SM_WBF0);
            unsigned afrag[2][2][4];
            {
                int rr = wm * 32 + (lane & 15);
                int kk = kc * 16 + ((lane >> 4) << 3);
                unsigned sw = (unsigned)((kk * 2) ^ ((rr & 7) << 4));
#pragma unroll
                for (int sub = 0; sub < 2; sub++) {
                    unsigned rb = (unsigned)((rr + sub * 16) * 256) + sw;
                    ldsm4(afrag[sub][0], smb + SM_ABF_HI + rb);
                    ldsm4(afrag[sub][1], smb + SM_ABF_LO + rb);
                }
            }
            const int bn = wn * 64 + (lane & 7);
            const unsigned bko = (lane & 8) ? 16u : 0u;
#pragma unroll
            for (int j = 0; j < 8; j++) {
                int n = bn + j * 8;
                unsigned sw = (unsigned)(n * 32) + (bko ^ (((n >> 2) & 1) << 4));
                unsigned bh[2], bl[2];
                ldsm2(bh, wb + sw);
                ldsm2(bl, wb + 8192 + sw);
                mma16816(&acc[(0 * 8 + j) * 4], afrag[0][0], bh);   // ah*wh
                mma16816(&acc[(1 * 8 + j) * 4], afrag[1][0], bh);
                mma16816(&acc[(0 * 8 + j) * 4], afrag[0][1], bh);   // al*wh
                mma16816(&acc[(1 * 8 + j) * 4], afrag[1][1], bh);
                mma16816(&acc[(0 * 8 + j) * 4], afrag[0][0], bl);   // ah*wl
                mma16816(&acc[(1 * 8 + j) * 4], afrag[1][0], bl);
            }
        } else {
            // ===== ffma warps: cols 256..511, fp32 (scalar A loads: stride 65) =====
            const float* wfp = (const float*)(sm + ((kc & 1) ? SM_WF1 : SM_WF0));
#pragma unroll
            for (int kk = 0; kk < 16; kk++) {
                const float* at = At + (kc * 16 + kk) * AT_STRIDE + rgrp * 8;
                float av[8];
#pragma unroll
                for (int i = 0; i < 8; i++) av[i] = at[i];   // LDS.32, 4-way bcast
                const float* wp = wfp + kk * 256 + fw * 32 + cg * 8;
                float4 w0 = *(const float4*)wp;
                float4 w1 = *(const float4*)(wp + 4);
                float wv[8] = {w0.x, w0.y, w0.z, w0.w, w1.x, w1.y, w1.z, w1.w};
#pragma unroll
                for (int i = 0; i < 8; i++)
#pragma unroll
                    for (int j = 0; j < 8; j++)
                        acc[i * 8 + j] = fmaf(av[i], wv[j], acc[i * 8 + j]);
            }
        }
    }
    __syncthreads();   // all smem reads done; smem becomes zbuf

    // ---- write z = acc*s + t into zbuf ----
    float* zb = (float*)sm;
    if (wid < 8) {
        const int cbase = wn * 64 + (lane & 3) * 2;
        const int rbase = wm * 32 + (lane >> 2);
#pragma unroll
        for (int sub = 0; sub < 2; sub++) {
#pragma unroll
            for (int j = 0; j < 8; j++) {
                int c = cbase + j * 8;
                float2 sv = *(float2*)&sS[c];
                float2 tv = *(float2*)&sT[c];
                int r = rbase + sub * 16;
                const float* a4 = &acc[(sub * 8 + j) * 4];
                float2 z0, z1;
                z0.x = fmaf(a4[0], sv.x, tv.x);
                z0.y = fmaf(a4[1], sv.y, tv.y);
                z1.x = fmaf(a4[2], sv.x, tv.x);
                z1.y = fmaf(a4[3], sv.y, tv.y);
                *(float2*)&zb[(size_t)r * ZSTRIDE + c] = z0;
                *(float2*)&zb[(size_t)(r + 8) * ZSTRIDE + c] = z1;
            }
        }
    } else {
        const int c0 = 256 + fw * 32 + cg * 8;
        float4 sv0 = *(float4*)&sS[c0], sv1 = *(float4*)&sS[c0 + 4];
        float4 tv0 = *(float4*)&sT[c0], tv1 = *(float4*)&sT[c0 + 4];
#pragma unroll
        for (int i = 0; i < 8; i++) {
            int r = rgrp * 8 + i;
            float4 z0, z1;
            z0.x = fmaf(acc[i * 8 + 0], sv0.x, tv0.x);
            z0.y = fmaf(acc[i * 8 + 1], sv0.y, tv0.y);
            z0.z = fmaf(acc[i * 8 + 2], sv0.z, tv0.z);
            z0.w = fmaf(acc[i * 8 + 3], sv0.w, tv0.w);
            z1.x = fmaf(acc[i * 8 + 4], sv1.x, tv1.x);
            z1.y = fmaf(acc[i * 8 + 5], sv1.y, tv1.y);
            z1.z = fmaf(acc[i * 8 + 6], sv1.z, tv1.z);
            z1.w = fmaf(acc[i * 8 + 7], sv1.w, tv1.w);
            *(float4*)&zb[(size_t)r * ZSTRIDE + c0] = z0;
            *(float4*)&zb[(size_t)r * ZSTRIDE + c0 + 4] = z1;
        }
    }
    __syncthreads();

    // ---- sparsemax: warp owns 4 rows, 16 vals/lane ----
    float v[4][16];
    const int lr0 = wid * 4;
#pragma unroll
    for (int r = 0; r < 4; r++) {
        size_t g = (size_t)(rowbase + lr0 + r);
#pragma unroll
        for (int sg = 0; sg < 4; sg++) {
            float4 b  = *(float4*)&zb[(size_t)(lr0 + r) * ZSTRIDE + sg * 128 + lane * 4];
            float4 pr = *(const float4*)&prior[g * FDIM + sg * 128 + lane * 4];
            v[r][sg * 4 + 0] = b.x * pr.x;
            v[r][sg * 4 + 1] = b.y * pr.y;
            v[r][sg * 4 + 2] = b.z * pr.z;
            v[r][sg * 4 + 3] = b.w * pr.w;
        }
    }

    float mx[4];
#pragma unroll
    for (int r = 0; r < 4; r++) {
        float m = v[r][0];
#pragma unroll
        for (int i = 1; i < 16; i++) m = fmaxf(m, v[r][i]);
        mx[r] = m;
    }
#pragma unroll
    for (int off = 16; off; off >>= 1)
#pragma unroll
        for (int r = 0; r < 4; r++)
            mx[r] = fmaxf(mx[r], __shfl_xor_sync(FULL_MASK, mx[r], off));

    float lo[4], hi[4];
#pragma unroll
    for (int r = 0; r < 4; r++) { lo[r] = mx[r] - 1.0f; hi[r] = mx[r]; }
#pragma unroll 1
    for (int it = 0; it < 17; ++it) {
        float mid[4], s4[4];
#pragma unroll
        for (int r = 0; r < 4; r++) { mid[r] = 0.5f * (lo[r] + hi[r]); s4[r] = 0.f; }
#pragma unroll
        for (int r = 0; r < 4; r++)
#pragma unroll
            for (int i = 0; i < 16; i++)
                s4[r] += fmaxf(v[r][i] - mid[r], 0.f);
#pragma unroll
        for (int off = 16; off; off >>= 1)
#pragma unroll
            for (int r = 0; r < 4; r++)
                s4[r] += __shfl_xor_sync(FULL_MASK, s4[r], off);
#pragma unroll
        for (int r = 0; r < 4; r++) {
            if (s4[r] >= 1.0f) lo[r] = mid[r]; else hi[r] = mid[r];
        }
    }

#pragma unroll
    for (int r = 0; r < 4; r++) {
        const float tau = 0.5f * (lo[r] + hi[r]);
        size_t g = (size_t)(rowbase + lr0 + r);
#pragma unroll
        for (int sg = 0; sg < 4; sg++) {
            float4 o;
            o.x = fmaxf(v[r][sg * 4 + 0] - tau, 0.f);
            o.y = fmaxf(v[r][sg * 4 + 1] - tau, 0.f);
            o.z = fmaxf(v[r][sg * 4 + 2] - tau, 0.f);
            o.w = fmaxf(v[r][sg * 4 + 3] - tau, 0.f);
            *(float4*)&out[g * FDIM + sg * 128 + lane * 4] = o;
        }
    }
}

// ================= launch =================
extern "C" void kernel_launch(void* const* d_in, const int* in_sizes, int n_in,
                              void* d_out, int out_size) {
    const float* A     = (const float*)d_in[0];
    const float* prior = (const float*)d_in[1];
    const float* W     = (const float*)d_in[2];
    const float* bias  = (const float*)d_in[3];
    const float* gamma = (const float*)d_in[4];
    const float* beta  = (const float*)d_in[5];
    const float* mmean = (const float*)d_in[6];
    const float* mvar  = (const float*)d_in[7];
    float* out = (float*)d_out;

    const int B = in_sizes[1] / FDIM;          // prior is [B, 512]

    conv_W_kernel<<<128, 512>>>(W);
    const int n2 = B * (KDIM / 2);
    conv_A_kernel<<<(n2 + 511) / 512, 512>>>(A, n2);

    cudaFuncSetAttribute(attn_dual_kernel,
                         cudaFuncAttributeMaxDynamicSharedMemorySize, SMEM_BYTES);
    attn_dual_kernel<<<B / MT, 512, SMEM_BYTES>>>(A, prior, W, bias, gamma, beta,
                                                  mmean, mvar, out);
}

// round 8
// speedup vs baseline: 1.1926x; 1.1926x over previous
#include <cuda_runtime.h>
#include <cuda_bf16.h>

#define FULL_MASK 0xffffffffu

constexpr int FDIM = 512;
constexpr int KDIM = 128;
constexpr int MT   = 64;          // rows per CTA
constexpr int BMAX = 65536;
constexpr float BN_EPS = 1e-3f;

// ---- scratch (device globals: allocation-free) ----
__device__ __nv_bfloat16 g_Ah[(size_t)BMAX * KDIM];
__device__ __nv_bfloat16 g_Al[(size_t)BMAX * KDIM];
__device__ __nv_bfloat16 g_Wh[(size_t)FDIM * KDIM];   // [f][k], k contiguous
__device__ __nv_bfloat16 g_Wl[(size_t)FDIM * KDIM];

// ---- smem layout (bytes) ----
// GEMM phase:   A_hi [0,16K)  A_lo [16K,32K)  W buf0 [32K,64K)  W buf1 [64K,96K)
//               (each W buf: hi 16K + lo 16K)
// epilogue:     zbuf [0, 64*516*4 = 132096) overlaps A/W
// always:       sS @133120 (2KB), sT @135168 (2KB)
constexpr int SM_A_HI = 0;
constexpr int SM_A_LO = 16384;
constexpr int SM_W0   = 32768;
constexpr int SM_W1   = 65536;
constexpr int ZSTRIDE = 516;              // floats
constexpr int SM_SS   = 133120;
constexpr int SM_TT   = 135168;
constexpr int SMEM_BYTES = 137216;

// ---- PTX helpers (base ISA only: no tcgen05/TMEM on this target) ----
__device__ __forceinline__ unsigned smem_u32(const void* p) {
    unsigned a;
    asm("{ .reg .u64 t; cvta.to.shared.u64 t, %1; cvt.u32.u64 %0, t; }" : "=r"(a) : "l"(p));
    return a;
}
__device__ __forceinline__ void cpa16(unsigned dst, const void* src) {
    asm volatile("cp.async.cg.shared.global [%0], [%1], 16;" :: "r"(dst), "l"(src));
}
__device__ __forceinline__ void cp_commit() {
    asm volatile("cp.async.commit_group;" ::: "memory");
}
__device__ __forceinline__ void cp_wait0() {
    asm volatile("cp.async.wait_group 0;" ::: "memory");
}
__device__ __forceinline__ void ldsm4(unsigned* r, unsigned addr) {
    asm volatile("ldmatrix.sync.aligned.m8n8.x4.shared.b16 {%0,%1,%2,%3}, [%4];"
        : "=r"(r[0]), "=r"(r[1]), "=r"(r[2]), "=r"(r[3]) : "r"(addr));
}
__device__ __forceinline__ void ldsm2(unsigned* r, unsigned addr) {
    asm volatile("ldmatrix.sync.aligned.m8n8.x2.shared.b16 {%0,%1}, [%2];"
        : "=r"(r[0]), "=r"(r[1]) : "r"(addr));
}
__device__ __forceinline__ void mma16816(float* d, const unsigned* a, const unsigned* b) {
    asm volatile(
        "mma.sync.aligned.m16n8k16.row.col.f32.bf16.bf16.f32 "
        "{%0,%1,%2,%3},{%4,%5,%6,%7},{%8,%9},{%0,%1,%2,%3};"
        : "+f"(d[0]), "+f"(d[1]), "+f"(d[2]), "+f"(d[3])
        : "r"(a[0]), "r"(a[1]), "r"(a[2]), "r"(a[3]), "r"(b[0]), "r"(b[1]));
}

// ================= conversion kernels =================
__global__ void conv_W_kernel(const float* __restrict__ W) {
    int idx = blockIdx.x * blockDim.x + threadIdx.x;   // 65536
    int k = idx >> 9;
    int f = idx & 511;
    float x = W[(size_t)k * FDIM + f];
    __nv_bfloat16 hi = __float2bfloat16(x);
    __nv_bfloat16 lo = __float2bfloat16(x - __bfloat162float(hi));
    g_Wh[(size_t)f * KDIM + k] = hi;
    g_Wl[(size_t)f * KDIM + k] = lo;
}

__global__ void conv_A_kernel(const float* __restrict__ A, int n2) {
    int i = blockIdx.x * blockDim.x + threadIdx.x;     // over float2's
    if (i >= n2) return;
    float2 x = ((const float2*)A)[i];
    __nv_bfloat16 h0 = __float2bfloat16(x.x);
    __nv_bfloat16 l0 = __float2bfloat16(x.x - __bfloat162float(h0));
    __nv_bfloat16 h1 = __float2bfloat16(x.y);
    __nv_bfloat16 l1 = __float2bfloat16(x.y - __bfloat162float(h1));
    __nv_bfloat162 hh; hh.x = h0; hh.y = h1;
    __nv_bfloat162 ll; ll.x = l0; ll.y = l1;
    ((__nv_bfloat162*)g_Ah)[i] = hh;
    ((__nv_bfloat162*)g_Al)[i] = ll;
}

// ================= main fused kernel =================
__global__ __launch_bounds__(512, 1)
void attn_mma_kernel(const float* __restrict__ prior,
                     const float* __restrict__ bias,
                     const float* __restrict__ gamma,
                     const float* __restrict__ beta,
                     const float* __restrict__ mmean,
                     const float* __restrict__ mvar,
                     float* __restrict__ out) {
    extern __shared__ char sm[];
    const unsigned smb = smem_u32(sm);
    float* sS = (float*)(sm + SM_SS);
    float* sT = (float*)(sm + SM_TT);

    const int tid  = threadIdx.x;
    const int wid  = tid >> 5;
    const int lane = tid & 31;
    const int wm   = wid >> 3;     // 0..1 : 32-row block
    const int wn   = wid & 7;      // 0..7 : 64-col slice
    const int rowbase = blockIdx.x * MT;

    // BN constants (bias folded): z = dot*s + t
    {
        float s = gamma[tid] * rsqrtf(mvar[tid] + BN_EPS);
        sS[tid] = s;
        sT[tid] = (bias[tid] - mmean[tid]) * s + beta[tid];
    }

    // ---- prologue: cp.async A tiles (hi+lo, swizzled) + W chunk 0 ----
#pragma unroll
    for (int p = 0; p < 4; p++) {
        int j   = p * 512 + tid;          // 2048 x uint4
        int sel = j >> 10;                // 0=hi 1=lo
        int rem = j & 1023;
        int r   = rem >> 4;
        int k8  = rem & 15;
        const __nv_bfloat16* src =
            (sel ? g_Al : g_Ah) + (size_t)(rowbase + r) * KDIM + k8 * 8;
        unsigned dst = smb + (sel ? SM_A_LO : SM_A_HI)
                     + r * 256 + ((k8 * 16) ^ ((r & 7) << 4));
        cpa16(dst, src);
    }
    {   // W chunk 0 -> buf0
#pragma unroll
        for (int p = 0; p < 4; p++) {
            int j   = p * 512 + tid;      // 2048 x uint4
            int sel = j >> 10;
            int rem = j & 1023;
            int n   = rem >> 1;
            int h   = rem & 1;
            const __nv_bfloat16* src =
                (sel ? g_Wl : g_Wh) + (size_t)n * KDIM + 0 * 16 + h * 8;
            unsigned dst = smb + SM_W0 + (sel ? 16384 : 0)
                         + n * 32 + ((h * 16) ^ (((n >> 2) & 1) << 4));
            cpa16(dst, src);
        }
    }
    cp_commit();

    float acc[2][8][4];
#pragma unroll
    for (int s = 0; s < 2; s++)
#pragma unroll
        for (int j = 0; j < 8; j++)
#pragma unroll
            for (int c = 0; c < 4; c++) acc[s][j][c] = 0.f;

    // ---- K loop: 8 chunks of 16, double-buffered W ----
#pragma unroll 1
    for (int kc = 0; kc < 8; kc++) {
        cp_wait0();
        __syncthreads();
        if (kc < 7) {
            const int base = ((kc + 1) & 1) ? SM_W1 : SM_W0;
#pragma unroll
            for (int p = 0; p < 4; p++) {
                int j   = p * 512 + tid;
                int sel = j >> 10;
                int rem = j & 1023;
                int n   = rem >> 1;
                int h   = rem & 1;
                const __nv_bfloat16* src =
                    (sel ? g_Wl : g_Wh) + (size_t)n * KDIM + (kc + 1) * 16 + h * 8;
                unsigned dst = smb + base + (sel ? 16384 : 0)
                             + n * 32 + ((h * 16) ^ (((n >> 2) & 1) << 4));
                cpa16(dst, src);
            }
            cp_commit();
        }
        const unsigned wb = smb + ((kc & 1) ? SM_W1 : SM_W0);

        // ---- load ALL fragments for this kc up front ----
        unsigned afrag[2][2][4];            // [sub m16][hi/lo]
        {
            int rr = wm * 32 + (lane & 15);
            int kk = kc * 16 + ((lane >> 4) << 3);
            unsigned sw = (unsigned)((kk * 2) ^ ((rr & 7) << 4));
#pragma unroll
            for (int sub = 0; sub < 2; sub++) {
                unsigned rb = (unsigned)((rr + sub * 16) * 256) + sw;
                ldsm4(afrag[sub][0], smb + SM_A_HI + rb);
                ldsm4(afrag[sub][1], smb + SM_A_LO + rb);
            }
        }
        unsigned bh[8][2], bl[8][2];
        {
            const int bn = wn * 64 + (lane & 7);
            const unsigned bko = (lane & 8) ? 16u : 0u;
#pragma unroll
            for (int j = 0; j < 8; j++) {
                int n = bn + j * 8;
                unsigned sw = (unsigned)(n * 32) + (bko ^ (((n >> 2) & 1) << 4));
                ldsm2(bh[j], wb + sw);
                ldsm2(bl[j], wb + 16384 + sw);
            }
        }

        // ---- 3 passes x 16 independent MMAs (dependents 16 insns apart) ----
#pragma unroll
        for (int j = 0; j < 8; j++) {       // pass 1: ah * wh
            mma16816(acc[0][j], afrag[0][0], bh[j]);
            mma16816(acc[1][j], afrag[1][0], bh[j]);
        }
#pragma unroll
        for (int j = 0; j < 8; j++) {       // pass 2: al * wh
            mma16816(acc[0][j], afrag[0][1], bh[j]);
            mma16816(acc[1][j], afrag[1][1], bh[j]);
        }
#pragma unroll
        for (int j = 0; j < 8; j++) {       // pass 3: ah * wl
            mma16816(acc[0][j], afrag[0][0], bl[j]);
            mma16816(acc[1][j], afrag[1][0], bl[j]);
        }
    }
    __syncthreads();   // all MMA reads done; smem becomes zbuf

    // ---- write z = acc*s + t into zbuf (fragment layout scatter) ----
    float* zb = (float*)sm;
    {
        const int cbase = wn * 64 + (lane & 3) * 2;
        const int rbase = wm * 32 + (lane >> 2);
#pragma unroll
        for (int sub = 0; sub < 2; sub++) {
#pragma unroll
            for (int j = 0; j < 8; j++) {
                int c = cbase + j * 8;
                float2 sv = *(float2*)&sS[c];
                float2 tv = *(float2*)&sT[c];
                int r = rbase + sub * 16;
                float2 z0, z1;
                z0.x = fmaf(acc[sub][j][0], sv.x, tv.x);
                z0.y = fmaf(acc[sub][j][1], sv.y, tv.y);
                z1.x = fmaf(acc[sub][j][2], sv.x, tv.x);
                z1.y = fmaf(acc[sub][j][3], sv.y, tv.y);
                *(float2*)&zb[(size_t)r * ZSTRIDE + c] = z0;
                *(float2*)&zb[(size_t)(r + 8) * ZSTRIDE + c] = z1;
            }
        }
    }
    __syncthreads();

    // ---- sparsemax: warp owns 4 rows, 16 vals/lane ----
    float v[4][16];
    const int lr0 = wid * 4;
#pragma unroll
    for (int r = 0; r < 4; r++) {
        size_t g = (size_t)(rowbase + lr0 + r);
#pragma unroll
        for (int sg = 0; sg < 4; sg++) {
            float4 b  = *(float4*)&zb[(size_t)(lr0 + r) * ZSTRIDE + sg * 128 + lane * 4];
            float4 pr = *(const float4*)&prior[g * FDIM + sg * 128 + lane * 4];
            v[r][sg * 4 + 0] = b.x * pr.x;
            v[r][sg * 4 + 1] = b.y * pr.y;
            v[r][sg * 4 + 2] = b.z * pr.z;
            v[r][sg * 4 + 3] = b.w * pr.w;
        }
    }

    float mx[4];
#pragma unroll
    for (int r = 0; r < 4; r++) {
        float m = v[r][0];
#pragma unroll
        for (int i = 1; i < 16; i++) m = fmaxf(m, v[r][i]);
        mx[r] = m;
    }
#pragma unroll
    for (int off = 16; off; off >>= 1)
#pragma unroll
        for (int r = 0; r < 4; r++)
            mx[r] = fmaxf(mx[r], __shfl_xor_sync(FULL_MASK, mx[r], off));

    float lo[4], hi[4];
#pragma unroll
    for (int r = 0; r < 4; r++) { lo[r] = mx[r] - 1.0f; hi[r] = mx[r]; }
#pragma unroll 1
    for (int it = 0; it < 17; ++it) {
        float mid[4], s4[4];
#pragma unroll
        for (int r = 0; r < 4; r++) { mid[r] = 0.5f * (lo[r] + hi[r]); s4[r] = 0.f; }
#pragma unroll
        for (int r = 0; r < 4; r++)
#pragma unroll
            for (int i = 0; i < 16; i++)
                s4[r] += fmaxf(v[r][i] - mid[r], 0.f);
#pragma unroll
        for (int off = 16; off; off >>= 1)
#pragma unroll
            for (int r = 0; r < 4; r++)
                s4[r] += __shfl_xor_sync(FULL_MASK, s4[r], off);
#pragma unroll
        for (int r = 0; r < 4; r++) {
            if (s4[r] >= 1.0f) lo[r] = mid[r]; else hi[r] = mid[r];
        }
    }

#pragma unroll
    for (int r = 0; r < 4; r++) {
        const float tau = 0.5f * (lo[r] + hi[r]);
        size_t g = (size_t)(rowbase + lr0 + r);
#pragma unroll
        for (int sg = 0; sg < 4; sg++) {
            float4 o;
            o.x = fmaxf(v[r][sg * 4 + 0] - tau, 0.f);
            o.y = fmaxf(v[r][sg * 4 + 1] - tau, 0.f);
            o.z = fmaxf(v[r][sg * 4 + 2] - tau, 0.f);
            o.w = fmaxf(v[r][sg * 4 + 3] - tau, 0.f);
            *(float4*)&out[g * FDIM + sg * 128 + lane * 4] = o;
        }
    }
}

// ================= launch =================
extern "C" void kernel_launch(void* const* d_in, const int* in_sizes, int n_in,
                              void* d_out, int out_size) {
    const float* A     = (const float*)d_in[0];
    const float* prior = (const float*)d_in[1];
    const float* W     = (const float*)d_in[2];
    const float* bias  = (const float*)d_in[3];
    const float* gamma = (const float*)d_in[4];
    const float* beta  = (const float*)d_in[5];
    const float* mmean = (const float*)d_in[6];
    const float* mvar  = (const float*)d_in[7];
    float* out = (float*)d_out;

    const int B = in_sizes[1] / FDIM;          // prior is [B, 512]

    conv_W_kernel<<<128, 512>>>(W);
    const int n2 = B * (KDIM / 2);
    conv_A_kernel<<<(n2 + 511) / 512, 512>>>(A, n2);

    cudaFuncSetAttribute(attn_mma_kernel,
                         cudaFuncAttributeMaxDynamicSharedMemorySize, SMEM_BYTES);
    attn_mma_kernel<<<B / MT, 512, SMEM_BYTES>>>(prior, bias, gamma, beta,
                                                 mmean, mvar, out);
}

// round 9
// speedup vs baseline: 1.4287x; 1.1979x over previous
#include <cuda_runtime.h>
#include <cuda_fp16.h>

#define FULL_MASK 0xffffffffu

constexpr int FDIM = 512;
constexpr int KDIM = 128;
constexpr int MT   = 64;          // rows per CTA
constexpr int BMAX = 65536;
constexpr float BN_EPS = 1e-3f;

// ---- scratch (device globals: allocation-free) ----
__device__ __half g_Ah[(size_t)BMAX * KDIM];
__device__ __half g_Al[(size_t)BMAX * KDIM];
__device__ __half g_Wh[(size_t)FDIM * KDIM];   // [f][k], k contiguous

// ---- smem layout (bytes) ----
// GEMM phase: A_hi [0,16K)  A_lo [16K,32K)  W buf0 [32K,48K)  W buf1 [48K,64K)
// epilogue:   zbuf [0, 64*516*4 = 132096) overlaps A/W
// always:     sS @133120 (2KB), sT @135168 (2KB)
constexpr int SM_A_HI = 0;
constexpr int SM_A_LO = 16384;
constexpr int SM_W0   = 32768;
constexpr int SM_W1   = 49152;
constexpr int ZSTRIDE = 516;              // floats
constexpr int SM_SS   = 133120;
constexpr int SM_TT   = 135168;
constexpr int SMEM_BYTES = 137216;

// ---- PTX helpers (base ISA only) ----
__device__ __forceinline__ unsigned smem_u32(const void* p) {
    unsigned a;
    asm("{ .reg .u64 t; cvta.to.shared.u64 t, %1; cvt.u32.u64 %0, t; }" : "=r"(a) : "l"(p));
    return a;
}
__device__ __forceinline__ void cpa16(unsigned dst, const void* src) {
    asm volatile("cp.async.cg.shared.global [%0], [%1], 16;" :: "r"(dst), "l"(src));
}
__device__ __forceinline__ void cp_commit() {
    asm volatile("cp.async.commit_group;" ::: "memory");
}
__device__ __forceinline__ void cp_wait0() {
    asm volatile("cp.async.wait_group 0;" ::: "memory");
}
__device__ __forceinline__ void ldsm4(unsigned* r, unsigned addr) {
    asm volatile("ldmatrix.sync.aligned.m8n8.x4.shared.b16 {%0,%1,%2,%3}, [%4];"
        : "=r"(r[0]), "=r"(r[1]), "=r"(r[2]), "=r"(r[3]) : "r"(addr));
}
__device__ __forceinline__ void ldsm2(unsigned* r, unsigned addr) {
    asm volatile("ldmatrix.sync.aligned.m8n8.x2.shared.b16 {%0,%1}, [%2];"
        : "=r"(r[0]), "=r"(r[1]) : "r"(addr));
}
__device__ __forceinline__ void mma16816(float* d, const unsigned* a, const unsigned* b) {
    asm volatile(
        "mma.sync.aligned.m16n8k16.row.col.f32.f16.f16.f32 "
        "{%0,%1,%2,%3},{%4,%5,%6,%7},{%8,%9},{%0,%1,%2,%3};"
        : "+f"(d[0]), "+f"(d[1]), "+f"(d[2]), "+f"(d[3])
        : "r"(a[0]), "r"(a[1]), "r"(a[2]), "r"(a[3]), "r"(b[0]), "r"(b[1]));
}

// ================= conversion kernels =================
__global__ void conv_W_kernel(const float* __restrict__ W) {
    int idx = blockIdx.x * blockDim.x + threadIdx.x;   // 65536
    int k = idx >> 9;
    int f = idx & 511;
    g_Wh[(size_t)f * KDIM + k] = __float2half(W[(size_t)k * FDIM + f]);
}

__global__ void conv_A_kernel(const float* __restrict__ A, int n2) {
    int i = blockIdx.x * blockDim.x + threadIdx.x;     // over float2's
    if (i >= n2) return;
    float2 x = ((const float2*)A)[i];
    __half h0 = __float2half(x.x);
    __half l0 = __float2half(x.x - __half2float(h0));
    __half h1 = __float2half(x.y);
    __half l1 = __float2half(x.y - __half2float(h1));
    __half2 hh; hh.x = h0; hh.y = h1;
    __half2 ll; ll.x = l0; ll.y = l1;
    ((__half2*)g_Ah)[i] = hh;
    ((__half2*)g_Al)[i] = ll;
}

// ================= main fused kernel =================
__global__ __launch_bounds__(512, 1)
void attn_mma_kernel(const float* __restrict__ prior,
                     const float* __restrict__ bias,
                     const float* __restrict__ gamma,
                     const float* __restrict__ beta,
                     const float* __restrict__ mmean,
                     const float* __restrict__ mvar,
                     float* __restrict__ out) {
    extern __shared__ char sm[];
    const unsigned smb = smem_u32(sm);
    float* sS = (float*)(sm + SM_SS);
    float* sT = (float*)(sm + SM_TT);

    const int tid  = threadIdx.x;
    const int wid  = tid >> 5;
    const int lane = tid & 31;
    const int wm   = wid >> 3;     // 0..1 : 32-row block
    const int wn   = wid & 7;      // 0..7 : 64-col slice
    const int rowbase = blockIdx.x * MT;

    // BN constants (bias folded): z = dot*s + t
    {
        float s = gamma[tid] * rsqrtf(mvar[tid] + BN_EPS);
        sS[tid] = s;
        sT[tid] = (bias[tid] - mmean[tid]) * s + beta[tid];
    }

    // ---- prologue: cp.async A tiles (hi+lo, swizzled) + W chunk 0 ----
#pragma unroll
    for (int p = 0; p < 4; p++) {
        int j   = p * 512 + tid;          // 2048 x uint4
        int sel = j >> 10;                // 0=hi 1=lo
        int rem = j & 1023;
        int r   = rem >> 4;
        int k8  = rem & 15;
        const __half* src =
            (sel ? g_Al : g_Ah) + (size_t)(rowbase + r) * KDIM + k8 * 8;
        unsigned dst = smb + (sel ? SM_A_LO : SM_A_HI)
                     + r * 256 + ((k8 * 16) ^ ((r & 7) << 4));
        cpa16(dst, src);
    }
    {   // W chunk 0 -> buf0: 1024 x uint4 (hi only)
#pragma unroll
        for (int p = 0; p < 2; p++) {
            int j = p * 512 + tid;
            int n = j >> 1;
            int h = j & 1;
            const __half* src = g_Wh + (size_t)n * KDIM + 0 * 16 + h * 8;
            unsigned dst = smb + SM_W0
                         + n * 32 + ((h * 16) ^ (((n >> 2) & 1) << 4));
            cpa16(dst, src);
        }
    }
    cp_commit();

    float acc[2][8][4];
#pragma unroll
    for (int s = 0; s < 2; s++)
#pragma unroll
        for (int j = 0; j < 8; j++)
#pragma unroll
            for (int c = 0; c < 4; c++) acc[s][j][c] = 0.f;

    // ---- K loop: 8 chunks of 16, double-buffered W ----
#pragma unroll 1
    for (int kc = 0; kc < 8; kc++) {
        cp_wait0();
        __syncthreads();
        if (kc < 7) {
            const int base = ((kc + 1) & 1) ? SM_W1 : SM_W0;
#pragma unroll
            for (int p = 0; p < 2; p++) {
                int j = p * 512 + tid;
                int n = j >> 1;
                int h = j & 1;
                const __half* src = g_Wh + (size_t)n * KDIM + (kc + 1) * 16 + h * 8;
                unsigned dst = smb + base
                             + n * 32 + ((h * 16) ^ (((n >> 2) & 1) << 4));
                cpa16(dst, src);
            }
            cp_commit();
        }
        const unsigned wb = smb + ((kc & 1) ? SM_W1 : SM_W0);

        // ---- load ALL fragments for this kc up front ----
        unsigned afrag[2][2][4];            // [sub m16][hi/lo]
        {
            int rr = wm * 32 + (lane & 15);
            int kk = kc * 16 + ((lane >> 4) << 3);
            unsigned sw = (unsigned)((kk * 2) ^ ((rr & 7) << 4));
#pragma unroll
            for (int sub = 0; sub < 2; sub++) {
                unsigned rb = (unsigned)((rr + sub * 16) * 256) + sw;
                ldsm4(afrag[sub][0], smb + SM_A_HI + rb);
                ldsm4(afrag[sub][1], smb + SM_A_LO + rb);
            }
        }
        unsigned bh[8][2];
        {
            const int bn = wn * 64 + (lane & 7);
            const unsigned bko = (lane & 8) ? 16u : 0u;
#pragma unroll
            for (int j = 0; j < 8; j++) {
                int n = bn + j * 8;
                unsigned sw = (unsigned)(n * 32) + (bko ^ (((n >> 2) & 1) << 4));
                ldsm2(bh[j], wb + sw);
            }
        }

        // ---- 2 passes x 16 independent MMAs ----
#pragma unroll
        for (int j = 0; j < 8; j++) {       // pass 1: ah * wh
            mma16816(acc[0][j], afrag[0][0], bh[j]);
            mma16816(acc[1][j], afrag[1][0], bh[j]);
        }
#pragma unroll
        for (int j = 0; j < 8; j++) {       // pass 2: al * wh
            mma16816(acc[0][j], afrag[0][1], bh[j]);
            mma16816(acc[1][j], afrag[1][1], bh[j]);
        }
    }
    __syncthreads();   // all MMA reads done; smem becomes zbuf

    // ---- write z = acc*s + t into zbuf (fragment layout scatter) ----
    float* zb = (float*)sm;
    {
        const int cbase = wn * 64 + (lane & 3) * 2;
        const int rbase = wm * 32 + (lane >> 2);
#pragma unroll
        for (int sub = 0; sub < 2; sub++) {
#pragma unroll
            for (int j = 0; j < 8; j++) {
                int c = cbase + j * 8;
                float2 sv = *(float2*)&sS[c];
                float2 tv = *(float2*)&sT[c];
                int r = rbase + sub * 16;
                float2 z0, z1;
                z0.x = fmaf(acc[sub][j][0], sv.x, tv.x);
                z0.y = fmaf(acc[sub][j][1], sv.y, tv.y);
                z1.x = fmaf(acc[sub][j][2], sv.x, tv.x);
                z1.y = fmaf(acc[sub][j][3], sv.y, tv.y);
                *(float2*)&zb[(size_t)r * ZSTRIDE + c] = z0;
                *(float2*)&zb[(size_t)(r + 8) * ZSTRIDE + c] = z1;
            }
        }
    }
    __syncthreads();

    // ---- sparsemax: warp owns 4 rows, 16 vals/lane ----
    float v[4][16];
    const int lr0 = wid * 4;
#pragma unroll
    for (int r = 0; r < 4; r++) {
        size_t g = (size_t)(rowbase + lr0 + r);
#pragma unroll
        for (int sg = 0; sg < 4; sg++) {
            float4 b  = *(float4*)&zb[(size_t)(lr0 + r) * ZSTRIDE + sg * 128 + lane * 4];
            float4 pr = *(const float4*)&prior[g * FDIM + sg * 128 + lane * 4];
            v[r][sg * 4 + 0] = b.x * pr.x;
            v[r][sg * 4 + 1] = b.y * pr.y;
            v[r][sg * 4 + 2] = b.z * pr.z;
            v[r][sg * 4 + 3] = b.w * pr.w;
        }
    }

    float mx[4];
#pragma unroll
    for (int r = 0; r < 4; r++) {
        float m = v[r][0];
#pragma unroll
        for (int i = 1; i < 16; i++) m = fmaxf(m, v[r][i]);
        mx[r] = m;
    }
#pragma unroll
    for (int off = 16; off; off >>= 1)
#pragma unroll
        for (int r = 0; r < 4; r++)
            mx[r] = fmaxf(mx[r], __shfl_xor_sync(FULL_MASK, mx[r], off));

    float lo[4], hi[4];
#pragma unroll
    for (int r = 0; r < 4; r++) { lo[r] = mx[r] - 1.0f; hi[r] = mx[r]; }
#pragma unroll 1
    for (int it = 0; it < 17; ++it) {
        float mid[4], s4[4];
#pragma unroll
        for (int r = 0; r < 4; r++) { mid[r] = 0.5f * (lo[r] + hi[r]); s4[r] = 0.f; }
#pragma unroll
        for (int r = 0; r < 4; r++)
#pragma unroll
            for (int i = 0; i < 16; i++)
                s4[r] += fmaxf(v[r][i] - mid[r], 0.f);
#pragma unroll
        for (int off = 16; off; off >>= 1)
#pragma unroll
            for (int r = 0; r < 4; r++)
                s4[r] += __shfl_xor_sync(FULL_MASK, s4[r], off);
#pragma unroll
        for (int r = 0; r < 4; r++) {
            if (s4[r] >= 1.0f) lo[r] = mid[r]; else hi[r] = mid[r];
        }
    }

#pragma unroll
    for (int r = 0; r < 4; r++) {
        const float tau = 0.5f * (lo[r] + hi[r]);
        size_t g = (size_t)(rowbase + lr0 + r);
#pragma unroll
        for (int sg = 0; sg < 4; sg++) {
            float4 o;
            o.x = fmaxf(v[r][sg * 4 + 0] - tau, 0.f);
            o.y = fmaxf(v[r][sg * 4 + 1] - tau, 0.f);
            o.z = fmaxf(v[r][sg * 4 + 2] - tau, 0.f);
            o.w = fmaxf(v[r][sg * 4 + 3] - tau, 0.f);
            *(float4*)&out[g * FDIM + sg * 128 + lane * 4] = o;
        }
    }
}

// ================= launch =================
extern "C" void kernel_launch(void* const* d_in, const int* in_sizes, int n_in,
                              void* d_out, int out_size) {
    const float* A     = (const float*)d_in[0];
    const float* prior = (const float*)d_in[1];
    const float* W     = (const float*)d_in[2];
    const float* bias  = (const float*)d_in[3];
    const float* gamma = (const float*)d_in[4];
    const float* beta  = (const float*)d_in[5];
    const float* mmean = (const float*)d_in[6];
    const float* mvar  = (const float*)d_in[7];
    float* out = (float*)d_out;

    const int B = in_sizes[1] / FDIM;          // prior is [B, 512]

    conv_W_kernel<<<128, 512>>>(W);
    const int n2 = B * (KDIM / 2);
    conv_A_kernel<<<(n2 + 511) / 512, 512>>>(A, n2);

    cudaFuncSetAttribute(attn_mma_kernel,
                         cudaFuncAttributeMaxDynamicSharedMemorySize, SMEM_BYTES);
    attn_mma_kernel<<<B / MT, 512, SMEM_BYTES>>>(prior, bias, gamma, beta,
                                                 mmean, mvar, out);
}

// round 11
// speedup vs baseline: 1.6701x; 1.1690x over previous
#include <cuda_runtime.h>
#include <cuda_fp16.h>

#define FULL_MASK 0xffffffffu

constexpr int FDIM = 512;
constexpr int KDIM = 128;
constexpr int MT   = 32;          // rows per CTA
constexpr int THREADS = 256;
constexpr float BN_EPS = 1e-3f;

// ---- scratch (device global: allocation-free) ----
__device__ __half g_Wh[(size_t)FDIM * KDIM];   // [f][k], k contiguous

// ---- smem layout (bytes) ----
// GEMM phase: A_hi [0,8K)  A_lo [8K,16K)  W buf0 [16K,32K)  W buf1 [32K,48K)
// epilogue:   zbuf [0, 32*516*4 = 66048) overlaps A/W
// always:     sS @66048 (2KB), sT @68096 (2KB)
constexpr int SM_A_HI = 0;
constexpr int SM_A_LO = 8192;
constexpr int SM_W0   = 16384;
constexpr int SM_W1   = 32768;
constexpr int ZSTRIDE = 516;              // floats
constexpr int SM_SS   = 66048;
constexpr int SM_TT   = 68096;
constexpr int SMEM_BYTES = 70144;

// ---- PTX helpers (base ISA only) ----
__device__ __forceinline__ unsigned smem_u32(const void* p) {
    unsigned a;
    asm("{ .reg .u64 t; cvta.to.shared.u64 t, %1; cvt.u32.u64 %0, t; }" : "=r"(a) : "l"(p));
    return a;
}
__device__ __forceinline__ unsigned h2_bits(__half2 h) {
    return *(unsigned*)&h;
}
__device__ __forceinline__ void cpa16(unsigned dst, const void* src) {
    asm volatile("cp.async.cg.shared.global [%0], [%1], 16;" :: "r"(dst), "l"(src));
}
__device__ __forceinline__ void cp_commit() {
    asm volatile("cp.async.commit_group;" ::: "memory");
}
__device__ __forceinline__ void cp_wait0() {
    asm volatile("cp.async.wait_group 0;" ::: "memory");
}
__device__ __forceinline__ void ldsm4(unsigned* r, unsigned addr) {
    asm volatile("ldmatrix.sync.aligned.m8n8.x4.shared.b16 {%0,%1,%2,%3}, [%4];"
        : "=r"(r[0]), "=r"(r[1]), "=r"(r[2]), "=r"(r[3]) : "r"(addr));
}
__device__ __forceinline__ void ldsm2(unsigned* r, unsigned addr) {
    asm volatile("ldmatrix.sync.aligned.m8n8.x2.shared.b16 {%0,%1}, [%2];"
        : "=r"(r[0]), "=r"(r[1]) : "r"(addr));
}
__device__ __forceinline__ void mma16816(float* d, const unsigned* a, const unsigned* b) {
    asm volatile(
        "mma.sync.aligned.m16n8k16.row.col.f32.f16.f16.f32 "
        "{%0,%1,%2,%3},{%4,%5,%6,%7},{%8,%9},{%0,%1,%2,%3};"
        : "+f"(d[0]), "+f"(d[1]), "+f"(d[2]), "+f"(d[3])
        : "r"(a[0]), "r"(a[1]), "r"(a[2]), "r"(a[3]), "r"(b[0]), "r"(b[1]));
}

// ================= W conversion kernel =================
__global__ void conv_W_kernel(const float* __restrict__ W) {
    int idx = blockIdx.x * blockDim.x + threadIdx.x;   // 65536
    int k = idx >> 9;
    int f = idx & 511;
    g_Wh[(size_t)f * KDIM + k] = __float2half(W[(size_t)k * FDIM + f]);
}

// ================= main fused kernel =================
__global__ __launch_bounds__(THREADS, 2)
void attn_mma_kernel(const float* __restrict__ A,
                     const float* __restrict__ prior,
                     const float* __restrict__ bias,
                     const float* __restrict__ gamma,
                     const float* __restrict__ beta,
                     const float* __restrict__ mmean,
                     const float* __restrict__ mvar,
                     float* __restrict__ out) {
    extern __shared__ char sm[];
    const unsigned smb = smem_u32(sm);
    float* sS = (float*)(sm + SM_SS);
    float* sT = (float*)(sm + SM_TT);

    const int tid  = threadIdx.x;
    const int wid  = tid >> 5;     // 0..7 : n64 column slice
    const int lane = tid & 31;
    const int rowbase = blockIdx.x * MT;

    // BN constants (bias folded): z = dot*s + t
#pragma unroll
    for (int f = tid; f < FDIM; f += THREADS) {
        float s = gamma[f] * rsqrtf(mvar[f] + BN_EPS);
        sS[f] = s;
        sT[f] = (bias[f] - mmean[f]) * s + beta[f];
    }

    // ---- prologue: W chunk 0 via cp.async ----
#pragma unroll
    for (int p = 0; p < 4; p++) {          // 1024 x uint4
        int j = p * THREADS + tid;
        int n = j >> 1;
        int h = j & 1;
        const __half* src = g_Wh + (size_t)n * KDIM + 0 * 16 + h * 8;
        unsigned dst = smb + SM_W0
                     + n * 32 + ((h * 16) ^ (((n >> 2) & 1) << 4));
        cpa16(dst, src);
    }
    cp_commit();

    // ---- A fp32 -> fp16 hi/lo, converted in-kernel into swizzled smem ----
#pragma unroll
    for (int p = 0; p < 4; p++) {
        int j  = p * THREADS + tid;        // 0..1023  (32 rows x 32 float4)
        int r  = j >> 5;
        int k4 = j & 31;
        float4 v = ((const float4*)A)[(size_t)(rowbase + r) * 32 + k4];
        __half2 h01 = __floats2half2_rn(v.x, v.y);
        __half2 h23 = __floats2half2_rn(v.z, v.w);
        float2 hf01 = __half22float2(h01);
        float2 hf23 = __half22float2(h23);
        __half2 l01 = __floats2half2_rn(v.x - hf01.x, v.y - hf01.y);
        __half2 l23 = __floats2half2_rn(v.z - hf23.x, v.w - hf23.y);
        int chunk = k4 >> 1;               // 16B chunk index within row
        int sub   = (k4 & 1) * 8;          // 8B sub-offset
        unsigned off = (unsigned)(r * 256 + ((chunk * 16) ^ ((r & 7) << 4)) + sub);
        uint2 hv; hv.x = h2_bits(h01); hv.y = h2_bits(h23);
        uint2 lv; lv.x = h2_bits(l01); lv.y = h2_bits(l23);
        *(uint2*)(sm + SM_A_HI + off) = hv;
        *(uint2*)(sm + SM_A_LO + off) = lv;
    }

    float acc[2][8][4];
#pragma unroll
    for (int s = 0; s < 2; s++)
#pragma unroll
        for (int j = 0; j < 8; j++)
#pragma unroll
            for (int c = 0; c < 4; c++) acc[s][j][c] = 0.f;

    // ---- K loop: 8 chunks of 16, double-buffered W ----
#pragma unroll 1
    for (int kc = 0; kc < 8; kc++) {
        cp_wait0();
        __syncthreads();
        if (kc < 7) {
            const int base = ((kc + 1) & 1) ? SM_W1 : SM_W0;
#pragma unroll
            for (int p = 0; p < 4; p++) {
                int j = p * THREADS + tid;
                int n = j >> 1;
                int h = j & 1;
                const __half* src = g_Wh + (size_t)n * KDIM + (kc + 1) * 16 + h * 8;
                unsigned dst = smb + base
                             + n * 32 + ((h * 16) ^ (((n >> 2) & 1) << 4));
                cpa16(dst, src);
            }
            cp_commit();
        }
        const unsigned wb = smb + ((kc & 1) ? SM_W1 : SM_W0);

        // ---- load ALL fragments for this kc up front ----
        unsigned afrag[2][2][4];            // [sub m16][hi/lo]
        {
            int rr = lane & 15;
            int kk = kc * 16 + ((lane >> 4) << 3);
            unsigned sw = (unsigned)((kk * 2) ^ ((rr & 7) << 4));
#pragma unroll
            for (int sub = 0; sub < 2; sub++) {
                unsigned rb = (unsigned)((rr + sub * 16) * 256) + sw;
                ldsm4(afrag[sub][0], smb + SM_A_HI + rb);
                ldsm4(afrag[sub][1], smb + SM_A_LO + rb);
            }
        }
        unsigned bh[8][2];
        {
            const int bn = wid * 64 + (lane & 7);
            const unsigned bko = (lane & 8) ? 16u : 0u;
#pragma unroll
            for (int j = 0; j < 8; j++) {
                int n = bn + j * 8;
                unsigned sw = (unsigned)(n * 32) + (bko ^ (((n >> 2) & 1) << 4));
                ldsm2(bh[j], wb + sw);
            }
        }

        // ---- 2 passes x 16 independent MMAs ----
#pragma unroll
        for (int j = 0; j < 8; j++) {       // pass 1: ah * wh
            mma16816(acc[0][j], afrag[0][0], bh[j]);
            mma16816(acc[1][j], afrag[1][0], bh[j]);
        }
#pragma unroll
        for (int j = 0; j < 8; j++) {       // pass 2: al * wh
            mma16816(acc[0][j], afrag[0][1], bh[j]);
            mma16816(acc[1][j], afrag[1][1], bh[j]);
        }
    }
    __syncthreads();   // all MMA reads done; smem becomes zbuf

    // ---- write z = acc*s + t into zbuf (fragment layout scatter) ----
    float* zb = (float*)sm;
    {
        const int cbase = wid * 64 + (lane & 3) * 2;
        const int rbase = lane >> 2;
#pragma unroll
        for (int sub = 0; sub < 2; sub++) {
#pragma unroll
            for (int j = 0; j < 8; j++) {
                int c = cbase + j * 8;
                float2 sv = *(float2*)&sS[c];
                float2 tv = *(float2*)&sT[c];
                int r = rbase + sub * 16;
                float2 z0, z1;
                z0.x = fmaf(acc[sub][j][0], sv.x, tv.x);
                z0.y = fmaf(acc[sub][j][1], sv.y, tv.y);
                z1.x = fmaf(acc[sub][j][2], sv.x, tv.x);
                z1.y = fmaf(acc[sub][j][3], sv.y, tv.y);
                *(float2*)&zb[(size_t)r * ZSTRIDE + c] = z0;
                *(float2*)&zb[(size_t)(r + 8) * ZSTRIDE + c] = z1;
            }
        }
    }
    __syncthreads();

    // ---- sparsemax: warp owns 4 rows, 16 vals/lane ----
    float v[4][16];
    const int lr0 = wid * 4;
#pragma unroll
    for (int r = 0; r < 4; r++) {
        size_t g = (size_t)(rowbase + lr0 + r);
#pragma unroll
        for (int sg = 0; sg < 4; sg++) {
            float4 b  = *(float4*)&zb[(size_t)(lr0 + r) * ZSTRIDE + sg * 128 + lane * 4];
            float4 pr = *(const float4*)&prior[g * FDIM + sg * 128 + lane * 4];
            v[r][sg * 4 + 0] = b.x * pr.x;
            v[r][sg * 4 + 1] = b.y * pr.y;
            v[r][sg * 4 + 2] = b.z * pr.z;
            v[r][sg * 4 + 3] = b.w * pr.w;
        }
    }

    float mx[4];
#pragma unroll
    for (int r = 0; r < 4; r++) {
        float m = v[r][0];
#pragma unroll
        for (int i = 1; i < 16; i++) m = fmaxf(m, v[r][i]);
        mx[r] = m;
    }
#pragma unroll
    for (int off = 16; off; off >>= 1)
#pragma unroll
        for (int r = 0; r < 4; r++)
            mx[r] = fmaxf(mx[r], __shfl_xor_sync(FULL_MASK, mx[r], off));

    float lo[4], hi[4];
#pragma unroll
    for (int r = 0; r < 4; r++) { lo[r] = mx[r] - 1.0f; hi[r] = mx[r]; }
#pragma unroll 1
    for (int it = 0; it < 17; ++it) {
        float mid[4], s4[4];
#pragma unroll
        for (int r = 0; r < 4; r++) { mid[r] = 0.5f * (lo[r] + hi[r]); s4[r] = 0.f; }
#pragma unroll
        for (int r = 0; r < 4; r++)
#pragma unroll
            for (int i = 0; i < 16; i++)
                s4[r] += fmaxf(v[r][i] - mid[r], 0.f);
#pragma unroll
        for (int off = 16; off; off >>= 1)
#pragma unroll
            for (int r = 0; r < 4; r++)
                s4[r] += __shfl_xor_sync(FULL_MASK, s4[r], off);
#pragma unroll
        for (int r = 0; r < 4; r++) {
            if (s4[r] >= 1.0f) lo[r] = mid[r]; else hi[r] = mid[r];
        }
    }

#pragma unroll
    for (int r = 0; r < 4; r++) {
        const float tau = 0.5f * (lo[r] + hi[r]);
        size_t g = (size_t)(rowbase + lr0 + r);
#pragma unroll
        for (int sg = 0; sg < 4; sg++) {
            float4 o;
            o.x = fmaxf(v[r][sg * 4 + 0] - tau, 0.f);
            o.y = fmaxf(v[r][sg * 4 + 1] - tau, 0.f);
            o.z = fmaxf(v[r][sg * 4 + 2] - tau, 0.f);
            o.w = fmaxf(v[r][sg * 4 + 3] - tau, 0.f);
            *(float4*)&out[g * FDIM + sg * 128 + lane * 4] = o;
        }
    }
}

// ================= launch =================
extern "C" void kernel_launch(void* const* d_in, const int* in_sizes, int n_in,
                              void* d_out, int out_size) {
    const float* A     = (const float*)d_in[0];
    const float* prior = (const float*)d_in[1];
    const float* W     = (const float*)d_in[2];
    const float* bias  = (const float*)d_in[3];
    const float* gamma = (const float*)d_in[4];
    const float* beta  = (const float*)d_in[5];
    const float* mmean = (const float*)d_in[6];
    const float* mvar  = (const float*)d_in[7];
    float* out = (float*)d_out;

    const int B = in_sizes[1] / FDIM;          // prior is [B, 512]

    conv_W_kernel<<<128, 512>>>(W);

    cudaFuncSetAttribute(attn_mma_kernel,
                         cudaFuncAttributeMaxDynamicSharedMemorySize, SMEM_BYTES);
    attn_mma_kernel<<<B / MT, THREADS, SMEM_BYTES>>>(A, prior, bias, gamma, beta,
                                                     mmean, mvar, out);
}